// round 14
// baseline (speedup 1.0000x reference)
#include <cuda_runtime.h>
#include <cuda_fp16.h>
#include <math.h>
#include <stdint.h>

#define C_DIM 1024
#define NSTR 4
#define HID 4096
#define NDC 24
#define T_MAX 8192

// ---------------- scratch ----------------
__device__ float g_WeffT[NDC * C_DIM];     // transposed: [j][c]
__device__ float g_hpost[T_MAX * NSTR];
__device__ float g_rsum[T_MAX * NSTR];

__device__ __half g_premix[(size_t)T_MAX * C_DIM];
__device__ __half g_h[(size_t)T_MAX * HID];
__device__ __half g_merged[(size_t)T_MAX * HID];
__device__ __half g_W1h[(size_t)C_DIM * HID];
__device__ __half g_W2h[(size_t)HID * C_DIM];
__device__ __half g_Woh[(size_t)HID * C_DIM];

// ---------------- helpers ----------------
__device__ __forceinline__ uint32_t sa(const void* p) {
    return (uint32_t)__cvta_generic_to_shared(p);
}
__device__ __forceinline__ void ldsm4(uint32_t* r, uint32_t addr) {
    asm volatile("ldmatrix.sync.aligned.m8n8.x4.shared.b16 {%0,%1,%2,%3},[%4];"
                 : "=r"(r[0]), "=r"(r[1]), "=r"(r[2]), "=r"(r[3]) : "r"(addr));
}
__device__ __forceinline__ void ldsm4t(uint32_t* r, uint32_t addr) {
    asm volatile("ldmatrix.sync.aligned.m8n8.x4.trans.shared.b16 {%0,%1,%2,%3},[%4];"
                 : "=r"(r[0]), "=r"(r[1]), "=r"(r[2]), "=r"(r[3]) : "r"(addr));
}
__device__ __forceinline__ void mma_f16(float* c, const uint32_t* a, const uint32_t* b) {
    asm volatile(
        "mma.sync.aligned.m16n8k16.row.col.f32.f16.f16.f32 "
        "{%0,%1,%2,%3},{%4,%5,%6,%7},{%8,%9},{%0,%1,%2,%3};"
        : "+f"(c[0]), "+f"(c[1]), "+f"(c[2]), "+f"(c[3])
        : "r"(a[0]), "r"(a[1]), "r"(a[2]), "r"(a[3]), "r"(b[0]), "r"(b[1]));
}
__device__ __forceinline__ float gelu_exact(float v) {
    return 0.5f * v * (1.f + erff(v * 0.70710678118654752f));
}
#define CP16(dst, src) \
    asm volatile("cp.async.cg.shared.global [%0], [%1], 16;" :: "r"(dst), "l"(src))
#define CP_COMMIT() asm volatile("cp.async.commit_group;" ::: "memory")
#define CP_WAIT1() asm volatile("cp.async.wait_group 1;" ::: "memory")

// ---------------- Weff precompute (transposed output) ----------------
__global__ void weff_kernel(const float* __restrict__ rmsw, const float* __restrict__ Wdyn) {
    int idx = blockIdx.x * blockDim.x + threadIdx.x;
    if (idx >= C_DIM * NDC) return;
    int c = idx / NDC, j = idx % NDC;
    float s = 0.f;
    #pragma unroll
    for (int st = 0; st < NSTR; st++) {
        int k = st * C_DIM + c;
        s += rmsw[k] * Wdyn[(size_t)k * NDC + j];
    }
    g_WeffT[j * C_DIM + c] = s;
}

// ---------------- fp32 -> fp16 convert (3 weights, one launch) ----------------
__global__ void cvt3_kernel(const float* __restrict__ W1, __half* __restrict__ H1,
                            const float* __restrict__ W2, __half* __restrict__ H2,
                            const float* __restrict__ W3, __half* __restrict__ H3,
                            int n4each) {
    int total = 3 * n4each;
    for (int i = blockIdx.x * blockDim.x + threadIdx.x; i < total; i += gridDim.x * blockDim.x) {
        int seg = i / n4each;
        int idx = i - seg * n4each;
        const float* W = (seg == 0) ? W1 : (seg == 1) ? W2 : W3;
        __half* H = (seg == 0) ? H1 : (seg == 1) ? H2 : H3;
        float4 v = *(const float4*)&W[(size_t)idx * 4];
        *(__half2*)&H[(size_t)idx * 4]     = __float22half2_rn(make_float2(v.x, v.y));
        *(__half2*)&H[(size_t)idx * 4 + 2] = __float22half2_rn(make_float2(v.z, v.w));
    }
}

// ---------------- gates: one WARP per token, coalesced WeffT ----------------
__global__ void gates_kernel(const float* __restrict__ x,
                             const float* __restrict__ bias_pre,
                             const float* __restrict__ bias_post,
                             const float* __restrict__ bias_res,
                             const float* __restrict__ alpha_pre,
                             const float* __restrict__ alpha_post,
                             const float* __restrict__ alpha_res) {
    int t = (blockIdx.x * blockDim.x + threadIdx.x) >> 5;
    int lane = threadIdx.x & 31;
    const float* xr = x + (size_t)t * C_DIM;

    float vals[25];
    #pragma unroll
    for (int j = 0; j < 25; j++) vals[j] = 0.f;

    #pragma unroll
    for (int i = 0; i < C_DIM / 128; i++) {
        int c = (i * 32 + lane) * 4;
        float4 xv = *(const float4*)&xr[c];
        vals[24] += xv.x * xv.x + xv.y * xv.y + xv.z * xv.z + xv.w * xv.w;
        #pragma unroll
        for (int j = 0; j < NDC; j++) {
            float4 wv = *(const float4*)&g_WeffT[j * C_DIM + c];
            vals[j] += xv.x * wv.x + xv.y * wv.y + xv.z * wv.z + xv.w * wv.w;
        }
    }
    #pragma unroll
    for (int o = 16; o; o >>= 1)
        #pragma unroll
        for (int j = 0; j < 25; j++)
            vals[j] += __shfl_down_sync(0xffffffffu, vals[j], o);

    float spre = 0.f;
    if (lane == 0) {
        float rms = sqrtf(vals[24] * (1.f / (float)C_DIM) + 1e-8f);
        float inv = 1.f / rms;
        float dyn[NDC];
        #pragma unroll
        for (int j = 0; j < NDC; j++) dyn[j] = vals[j] * inv;

        float ap = alpha_pre[0], apo = alpha_post[0], ar = alpha_res[0];
        #pragma unroll
        for (int s = 0; s < NSTR; s++)
            spre += 1.f / (1.f + expf(-(ap * dyn[s] + bias_pre[s])));
        float hp[NSTR];
        #pragma unroll
        for (int s = 0; s < NSTR; s++)
            hp[s] = 2.f / (1.f + expf(-(apo * dyn[NSTR + s] + bias_post[s])));

        float M[NSTR][NSTR];
        #pragma unroll
        for (int i = 0; i < NSTR; i++)
            #pragma unroll
            for (int j = 0; j < NSTR; j++)
                M[i][j] = expf(ar * dyn[2 * NSTR + i * NSTR + j] + bias_res[i * NSTR + j]);
        for (int it = 0; it < 20; it++) {
            float cs[NSTR];
            #pragma unroll
            for (int j = 0; j < NSTR; j++) {
                cs[j] = 0.f;
                #pragma unroll
                for (int i = 0; i < NSTR; i++) cs[j] += M[i][j];
                cs[j] = 1.f / (cs[j] + 1e-8f);
            }
            #pragma unroll
            for (int i = 0; i < NSTR; i++) {
                float rs = 0.f;
                #pragma unroll
                for (int j = 0; j < NSTR; j++) { M[i][j] *= cs[j]; rs += M[i][j]; }
                rs = 1.f / (rs + 1e-8f);
                #pragma unroll
                for (int j = 0; j < NSTR; j++) M[i][j] *= rs;
            }
        }
        #pragma unroll
        for (int s = 0; s < NSTR; s++) {
            float rsum = 0.f;
            #pragma unroll
            for (int j = 0; j < NSTR; j++) rsum += M[s][j];
            g_hpost[t * NSTR + s] = hp[s];
            g_rsum[t * NSTR + s] = rsum;
        }
    }
    spre = __shfl_sync(0xffffffffu, spre, 0);

    #pragma unroll
    for (int i = 0; i < C_DIM / 128; i++) {
        int c = (i * 32 + lane) * 4;
        float4 xv = *(const float4*)&xr[c];
        __half2 p0 = __float22half2_rn(make_float2(spre * xv.x, spre * xv.y));
        __half2 p1 = __float22half2_rn(make_float2(spre * xv.z, spre * xv.w));
        *(__half2*)&g_premix[(size_t)t * C_DIM + c]     = p0;
        *(__half2*)&g_premix[(size_t)t * C_DIM + c + 2] = p1;
    }
}

// ---------------- fp16 GEMM: 128x128x64 block, 4 warps (2x2), warp tile 64x64 ----------------
#define BM 128
#define BN 128
#define BK 64
#define STAGES 3
#define NTHREADS 128
#define APITCH 144            // 64*2 + 16 pad (36 words == 4 mod 32)
#define BPITCH 272            // 128*2 + 16 pad
#define A_OFF 0
#define B_OFF (BM * APITCH)                  // 18432
#define SSTRIDE (B_OFF + BK * BPITCH)        // 18432 + 17408 = 35840
#define SMEM_TOTAL (STAGES * SSTRIDE)        // 107520 (x2 CTAs = 215KB/SM)

__device__ __forceinline__ void load_stage(
    uint32_t st, int tid,
    const __half* __restrict__ A, const __half* __restrict__ B,
    int bm, int bn, int K, int N, int kt) {
    // A: 128 rows x 64 cols fp16 = 1024 chunks of 16B; 8 per thread (128 threads)
    #pragma unroll
    for (int i = 0; i < 8; i++) {
        int q = tid + i * NTHREADS;
        int r = q >> 3, c8 = (q & 7) * 8;
        CP16(st + A_OFF + r * APITCH + c8 * 2, A + (size_t)(bm + r) * K + kt * BK + c8);
    }
    // B: 64 rows x 128 cols fp16 = 1024 chunks; 8 per thread
    #pragma unroll
    for (int i = 0; i < 8; i++) {
        int q = tid + i * NTHREADS;
        int r = q >> 4, c8 = (q & 15) * 8;
        CP16(st + B_OFF + r * BPITCH + c8 * 2, B + (size_t)(kt * BK + r) * N + bn + c8);
    }
}

// EPI 0: gelu -> Ch fp16 (stride N). EPI 2: fused merge -> Ch fp16 (stride HID).
// EPI 3: +bias +resid -> fp32 outF.
template <int EPI>
__global__ void __launch_bounds__(NTHREADS, 2) mma_gemm(
    const __half* __restrict__ A, const __half* __restrict__ B,
    const float* __restrict__ bias, const float* __restrict__ xin,
    __half* __restrict__ Ch, float* __restrict__ outF, int M, int N, int K) {
    extern __shared__ char smem[];
    uint32_t sb = sa(smem);
    int tid = threadIdx.x;
    int lane = tid & 31;
    int wid = tid >> 5;
    int wm = wid & 1;      // 2 warps along M (64 rows)
    int wn = wid >> 1;     // 2 warps along N (64 cols)
    int bm = blockIdx.y * BM, bn = blockIdx.x * BN;
    int KT = K / BK;

    // prologue: stages 0,1
    load_stage(sb, tid, A, B, bm, bn, K, N, 0);
    CP_COMMIT();
    load_stage(sb + SSTRIDE, tid, A, B, bm, bn, K, N, 1);
    CP_COMMIT();

    float acc[4][8][4];
    #pragma unroll
    for (int i = 0; i < 4; i++)
        #pragma unroll
        for (int j = 0; j < 8; j++)
            #pragma unroll
            for (int q = 0; q < 4; q++) acc[i][j][q] = 0.f;

    int a_m = wm * 64 + (lane & 15);
    int a_k = (lane >> 4) * 8;
    int b_k = ((lane >> 3) & 1) * 8 + (lane & 7);
    int b_n0 = wn * 64 + (lane >> 4) * 8;

    int slot = 0, slot_ld = 2;
    for (int kt = 0; kt < KT; kt++) {
        CP_WAIT1();
        __syncthreads();
        if (kt + 2 < KT)
            load_stage(sb + slot_ld * SSTRIDE, tid, A, B, bm, bn, K, N, kt + 2);
        CP_COMMIT();

        uint32_t st = sb + slot * SSTRIDE;
        #pragma unroll
        for (int u = 0; u < BK / 16; u++) {
            uint32_t a[4][4], b[8][2];
            #pragma unroll
            for (int mt = 0; mt < 4; mt++)
                ldsm4(a[mt], st + A_OFF + (a_m + mt * 16) * APITCH + (u * 16 + a_k) * 2);
            #pragma unroll
            for (int nr = 0; nr < 4; nr++) {
                uint32_t r[4];
                ldsm4t(r, st + B_OFF + (u * 16 + b_k) * BPITCH + (b_n0 + nr * 16) * 2);
                b[nr * 2][0] = r[0]; b[nr * 2][1] = r[1];
                b[nr * 2 + 1][0] = r[2]; b[nr * 2 + 1][1] = r[3];
            }
            #pragma unroll
            for (int mt = 0; mt < 4; mt++)
                #pragma unroll
                for (int nt = 0; nt < 8; nt++)
                    mma_f16(acc[mt][nt], a[mt], b[nt]);
        }
        slot = (slot == STAGES - 1) ? 0 : slot + 1;
        slot_ld = (slot_ld == STAGES - 1) ? 0 : slot_ld + 1;
    }

    // -------- epilogue --------
    int g = lane >> 2, tg = lane & 3;
    #pragma unroll
    for (int mt = 0; mt < 4; mt++) {
        #pragma unroll
        for (int half_ = 0; half_ < 2; half_++) {
            int row = bm + wm * 64 + mt * 16 + g + half_ * 8;
            float rs[NSTR], hp[NSTR];
            if (EPI == 2) {
                float4 r4 = *(const float4*)&g_rsum[row * NSTR];
                float4 h4 = *(const float4*)&g_hpost[row * NSTR];
                rs[0] = r4.x; rs[1] = r4.y; rs[2] = r4.z; rs[3] = r4.w;
                hp[0] = h4.x; hp[1] = h4.y; hp[2] = h4.z; hp[3] = h4.w;
            }
            #pragma unroll
            for (int nt = 0; nt < 8; nt++) {
                int col = bn + wn * 64 + nt * 8 + tg * 2;
                float2 bv = *(const float2*)&bias[col];
                float v0 = acc[mt][nt][half_ * 2 + 0] + bv.x;
                float v1 = acc[mt][nt][half_ * 2 + 1] + bv.y;
                if (EPI == 0) {
                    v0 = gelu_exact(v0);
                    v1 = gelu_exact(v1);
                    *(__half2*)&Ch[(size_t)row * N + col] =
                        __float22half2_rn(make_float2(v0, v1));
                } else if (EPI == 2) {
                    float2 xv = *(const float2*)&xin[(size_t)row * N + col];
                    #pragma unroll
                    for (int s = 0; s < NSTR; s++) {
                        float m0 = rs[s] * xv.x + hp[s] * v0;
                        float m1 = rs[s] * xv.y + hp[s] * v1;
                        *(__half2*)&Ch[(size_t)row * HID + s * C_DIM + col] =
                            __float22half2_rn(make_float2(m0, m1));
                    }
                } else {
                    float2 xv = *(const float2*)&xin[(size_t)row * N + col];
                    float2 o;
                    o.x = v0 + xv.x;
                    o.y = v1 + xv.y;
                    *(float2*)&outF[(size_t)row * N + col] = o;
                }
            }
        }
    }
}

// ---------------- launch ----------------
extern "C" void kernel_launch(void* const* d_in, const int* in_sizes, int n_in,
                              void* d_out, int out_size) {
    const float* x         = (const float*)d_in[0];
    const float* rms_w     = (const float*)d_in[1];
    const float* W_dyn     = (const float*)d_in[2];
    const float* bias_pre  = (const float*)d_in[3];
    const float* bias_post = (const float*)d_in[4];
    const float* bias_res  = (const float*)d_in[5];
    const float* alpha_pre = (const float*)d_in[6];
    const float* alpha_post= (const float*)d_in[7];
    const float* alpha_res = (const float*)d_in[8];
    const float* W1        = (const float*)d_in[9];
    const float* b1        = (const float*)d_in[10];
    const float* W2        = (const float*)d_in[11];
    const float* b2        = (const float*)d_in[12];
    const float* Wout      = (const float*)d_in[13];
    const float* bout      = (const float*)d_in[14];
    float* out = (float*)d_out;

    int T = in_sizes[0] / C_DIM;   // 8192

    __half *premix, *h, *merged, *w1h, *w2h, *woh;
    cudaGetSymbolAddress((void**)&premix, g_premix);
    cudaGetSymbolAddress((void**)&h, g_h);
    cudaGetSymbolAddress((void**)&merged, g_merged);
    cudaGetSymbolAddress((void**)&w1h, g_W1h);
    cudaGetSymbolAddress((void**)&w2h, g_W2h);
    cudaGetSymbolAddress((void**)&woh, g_Woh);

    cudaFuncSetAttribute(mma_gemm<0>, cudaFuncAttributeMaxDynamicSharedMemorySize, SMEM_TOTAL);
    cudaFuncSetAttribute(mma_gemm<2>, cudaFuncAttributeMaxDynamicSharedMemorySize, SMEM_TOTAL);
    cudaFuncSetAttribute(mma_gemm<3>, cudaFuncAttributeMaxDynamicSharedMemorySize, SMEM_TOTAL);

    // 1. prep
    weff_kernel<<<(C_DIM * NDC + 255) / 256, 256>>>(rms_w, W_dyn);
    cvt3_kernel<<<3072, 256>>>(W1, w1h, W2, w2h, Wout, woh, C_DIM * HID / 4);
    // 2. gates + sinkhorn + premix (warp per token)
    gates_kernel<<<T / 8, 256>>>(x, bias_pre, bias_post, bias_res,
                                 alpha_pre, alpha_post, alpha_res);
    // 3. h = gelu(premix @ W1 + b1)
    mma_gemm<0><<<dim3(HID / BN, T / BM), NTHREADS, SMEM_TOTAL>>>(
        premix, w1h, b1, nullptr, h, nullptr, T, HID, C_DIM);
    // 4. fout = h @ W2 + b2, fused merge -> merged
    mma_gemm<2><<<dim3(C_DIM / BN, T / BM), NTHREADS, SMEM_TOTAL>>>(
        h, w2h, b2, x, merged, nullptr, T, C_DIM, HID);
    // 5. out = merged @ Wout + bout + x
    mma_gemm<3><<<dim3(C_DIM / BN, T / BM), NTHREADS, SMEM_TOTAL>>>(
        merged, woh, bout, x, nullptr, out, T, C_DIM, HID);
}

// round 15
// speedup vs baseline: 1.1584x; 1.1584x over previous
#include <cuda_runtime.h>
#include <cuda_fp16.h>
#include <math.h>
#include <stdint.h>

#define C_DIM 1024
#define NSTR 4
#define HID 4096
#define NDC 24
#define T_MAX 8192

// ---------------- scratch ----------------
__device__ float g_WeffT[NDC * C_DIM];     // transposed: [j][c]
__device__ float g_hpost[T_MAX * NSTR];
__device__ float g_rsum[T_MAX * NSTR];

__device__ __half g_premix[(size_t)T_MAX * C_DIM];
__device__ __half g_h[(size_t)T_MAX * HID];
__device__ __half g_merged[(size_t)T_MAX * HID];
__device__ __half g_W1h[(size_t)C_DIM * HID];
__device__ __half g_W2h[(size_t)HID * C_DIM];
__device__ __half g_Woh[(size_t)HID * C_DIM];

// ---------------- helpers ----------------
__device__ __forceinline__ uint32_t sa(const void* p) {
    return (uint32_t)__cvta_generic_to_shared(p);
}
__device__ __forceinline__ void ldsm4(uint32_t* r, uint32_t addr) {
    asm volatile("ldmatrix.sync.aligned.m8n8.x4.shared.b16 {%0,%1,%2,%3},[%4];"
                 : "=r"(r[0]), "=r"(r[1]), "=r"(r[2]), "=r"(r[3]) : "r"(addr));
}
__device__ __forceinline__ void ldsm4t(uint32_t* r, uint32_t addr) {
    asm volatile("ldmatrix.sync.aligned.m8n8.x4.trans.shared.b16 {%0,%1,%2,%3},[%4];"
                 : "=r"(r[0]), "=r"(r[1]), "=r"(r[2]), "=r"(r[3]) : "r"(addr));
}
__device__ __forceinline__ void mma_f16(float* c, const uint32_t* a, const uint32_t* b) {
    asm volatile(
        "mma.sync.aligned.m16n8k16.row.col.f32.f16.f16.f32 "
        "{%0,%1,%2,%3},{%4,%5,%6,%7},{%8,%9},{%0,%1,%2,%3};"
        : "+f"(c[0]), "+f"(c[1]), "+f"(c[2]), "+f"(c[3])
        : "r"(a[0]), "r"(a[1]), "r"(a[2]), "r"(a[3]), "r"(b[0]), "r"(b[1]));
}
__device__ __forceinline__ float gelu_exact(float v) {
    return 0.5f * v * (1.f + erff(v * 0.70710678118654752f));
}
#define CP16(dst, src) \
    asm volatile("cp.async.cg.shared.global [%0], [%1], 16;" :: "r"(dst), "l"(src))
#define CP_COMMIT() asm volatile("cp.async.commit_group;" ::: "memory")
#define CP_WAIT2() asm volatile("cp.async.wait_group 2;" ::: "memory")

// ---------------- Weff precompute (transposed output) ----------------
__global__ void weff_kernel(const float* __restrict__ rmsw, const float* __restrict__ Wdyn) {
    int idx = blockIdx.x * blockDim.x + threadIdx.x;
    if (idx >= C_DIM * NDC) return;
    int c = idx / NDC, j = idx % NDC;
    float s = 0.f;
    #pragma unroll
    for (int st = 0; st < NSTR; st++) {
        int k = st * C_DIM + c;
        s += rmsw[k] * Wdyn[(size_t)k * NDC + j];
    }
    g_WeffT[j * C_DIM + c] = s;
}

// ---------------- fp32 -> fp16 convert (3 weights, one launch) ----------------
__global__ void cvt3_kernel(const float* __restrict__ W1, __half* __restrict__ H1,
                            const float* __restrict__ W2, __half* __restrict__ H2,
                            const float* __restrict__ W3, __half* __restrict__ H3,
                            int n4each) {
    int total = 3 * n4each;
    for (int i = blockIdx.x * blockDim.x + threadIdx.x; i < total; i += gridDim.x * blockDim.x) {
        int seg = i / n4each;
        int idx = i - seg * n4each;
        const float* W = (seg == 0) ? W1 : (seg == 1) ? W2 : W3;
        __half* H = (seg == 0) ? H1 : (seg == 1) ? H2 : H3;
        float4 v = *(const float4*)&W[(size_t)idx * 4];
        *(__half2*)&H[(size_t)idx * 4]     = __float22half2_rn(make_float2(v.x, v.y));
        *(__half2*)&H[(size_t)idx * 4 + 2] = __float22half2_rn(make_float2(v.z, v.w));
    }
}

// ---------------- gates: one WARP per token, coalesced WeffT ----------------
__global__ void gates_kernel(const float* __restrict__ x,
                             const float* __restrict__ bias_pre,
                             const float* __restrict__ bias_post,
                             const float* __restrict__ bias_res,
                             const float* __restrict__ alpha_pre,
                             const float* __restrict__ alpha_post,
                             const float* __restrict__ alpha_res) {
    int t = (blockIdx.x * blockDim.x + threadIdx.x) >> 5;
    int lane = threadIdx.x & 31;
    const float* xr = x + (size_t)t * C_DIM;

    float vals[25];
    #pragma unroll
    for (int j = 0; j < 25; j++) vals[j] = 0.f;

    #pragma unroll
    for (int i = 0; i < C_DIM / 128; i++) {
        int c = (i * 32 + lane) * 4;
        float4 xv = *(const float4*)&xr[c];
        vals[24] += xv.x * xv.x + xv.y * xv.y + xv.z * xv.z + xv.w * xv.w;
        #pragma unroll
        for (int j = 0; j < NDC; j++) {
            float4 wv = *(const float4*)&g_WeffT[j * C_DIM + c];
            vals[j] += xv.x * wv.x + xv.y * wv.y + xv.z * wv.z + xv.w * wv.w;
        }
    }
    #pragma unroll
    for (int o = 16; o; o >>= 1)
        #pragma unroll
        for (int j = 0; j < 25; j++)
            vals[j] += __shfl_down_sync(0xffffffffu, vals[j], o);

    float spre = 0.f;
    if (lane == 0) {
        float rms = sqrtf(vals[24] * (1.f / (float)C_DIM) + 1e-8f);
        float inv = 1.f / rms;
        float dyn[NDC];
        #pragma unroll
        for (int j = 0; j < NDC; j++) dyn[j] = vals[j] * inv;

        float ap = alpha_pre[0], apo = alpha_post[0], ar = alpha_res[0];
        #pragma unroll
        for (int s = 0; s < NSTR; s++)
            spre += 1.f / (1.f + expf(-(ap * dyn[s] + bias_pre[s])));
        float hp[NSTR];
        #pragma unroll
        for (int s = 0; s < NSTR; s++)
            hp[s] = 2.f / (1.f + expf(-(apo * dyn[NSTR + s] + bias_post[s])));

        float M[NSTR][NSTR];
        #pragma unroll
        for (int i = 0; i < NSTR; i++)
            #pragma unroll
            for (int j = 0; j < NSTR; j++)
                M[i][j] = expf(ar * dyn[2 * NSTR + i * NSTR + j] + bias_res[i * NSTR + j]);
        for (int it = 0; it < 20; it++) {
            float cs[NSTR];
            #pragma unroll
            for (int j = 0; j < NSTR; j++) {
                cs[j] = 0.f;
                #pragma unroll
                for (int i = 0; i < NSTR; i++) cs[j] += M[i][j];
                cs[j] = 1.f / (cs[j] + 1e-8f);
            }
            #pragma unroll
            for (int i = 0; i < NSTR; i++) {
                float rs = 0.f;
                #pragma unroll
                for (int j = 0; j < NSTR; j++) { M[i][j] *= cs[j]; rs += M[i][j]; }
                rs = 1.f / (rs + 1e-8f);
                #pragma unroll
                for (int j = 0; j < NSTR; j++) M[i][j] *= rs;
            }
        }
        #pragma unroll
        for (int s = 0; s < NSTR; s++) {
            float rsum = 0.f;
            #pragma unroll
            for (int j = 0; j < NSTR; j++) rsum += M[s][j];
            g_hpost[t * NSTR + s] = hp[s];
            g_rsum[t * NSTR + s] = rsum;
        }
    }
    spre = __shfl_sync(0xffffffffu, spre, 0);

    #pragma unroll
    for (int i = 0; i < C_DIM / 128; i++) {
        int c = (i * 32 + lane) * 4;
        float4 xv = *(const float4*)&xr[c];
        __half2 p0 = __float22half2_rn(make_float2(spre * xv.x, spre * xv.y));
        __half2 p1 = __float22half2_rn(make_float2(spre * xv.z, spre * xv.w));
        *(__half2*)&g_premix[(size_t)t * C_DIM + c]     = p0;
        *(__half2*)&g_premix[(size_t)t * C_DIM + c + 2] = p1;
    }
}

// ---------------- fp16 GEMM: 128x128x32 block, 4 warps (2x2), warp tile 64x64 ----------------
#define BM 128
#define BN 128
#define BK 32
#define STAGES 4
#define NTHREADS 128
#define APITCH 80             // 32*2 + 16 pad
#define BPITCH 272            // 128*2 + 16 pad
#define A_OFF 0
#define B_OFF (BM * APITCH)                  // 10240
#define SSTRIDE (B_OFF + BK * BPITCH)        // 18944
#define SMEM_TOTAL (STAGES * SSTRIDE)        // 75776

__device__ __forceinline__ void load_stage(
    uint32_t st, int tid,
    const __half* __restrict__ A, const __half* __restrict__ B,
    int bm, int bn, int K, int N, int kt) {
    #pragma unroll
    for (int i = 0; i < 4; i++) {
        int q = tid + i * NTHREADS;
        int r = q >> 2, c8 = (q & 3) * 8;
        CP16(st + A_OFF + r * APITCH + c8 * 2, A + (size_t)(bm + r) * K + kt * BK + c8);
    }
    #pragma unroll
    for (int i = 0; i < 4; i++) {
        int q = tid + i * NTHREADS;
        int r = q >> 4, c8 = (q & 15) * 8;
        CP16(st + B_OFF + r * BPITCH + c8 * 2, B + (size_t)(kt * BK + r) * N + bn + c8);
    }
}

// EPI 0: gelu -> Ch fp16 (stride N). EPI 2: fused merge -> Ch fp16 (stride HID).
// EPI 3: +bias +resid -> fp32 outF.
template <int EPI>
__global__ void __launch_bounds__(NTHREADS, 2) mma_gemm(
    const __half* __restrict__ A, const __half* __restrict__ B,
    const float* __restrict__ bias, const float* __restrict__ xin,
    __half* __restrict__ Ch, float* __restrict__ outF, int M, int N, int K) {
    extern __shared__ char smem[];
    uint32_t sb = sa(smem);
    int tid = threadIdx.x;
    int lane = tid & 31;
    int wid = tid >> 5;
    int wm = wid & 1;      // 2 warps along M (64 rows)
    int wn = wid >> 1;     // 2 warps along N (64 cols)
    int bm = blockIdx.y * BM, bn = blockIdx.x * BN;
    int KT = K / BK;

    // prologue: stages 0..2
    #pragma unroll
    for (int s = 0; s < STAGES - 1; s++) {
        load_stage(sb + s * SSTRIDE, tid, A, B, bm, bn, K, N, s);
        CP_COMMIT();
    }

    float acc[4][8][4];
    #pragma unroll
    for (int i = 0; i < 4; i++)
        #pragma unroll
        for (int j = 0; j < 8; j++)
            #pragma unroll
            for (int q = 0; q < 4; q++) acc[i][j][q] = 0.f;

    int a_m = wm * 64 + (lane & 15);
    int a_k = (lane >> 4) * 8;
    int b_k = ((lane >> 3) & 1) * 8 + (lane & 7);
    int b_n0 = wn * 64 + (lane >> 4) * 8;

    int slot = 0, slot_ld = STAGES - 1;
    for (int kt = 0; kt < KT; kt++) {
        CP_WAIT2();
        __syncthreads();
        if (kt + STAGES - 1 < KT)
            load_stage(sb + slot_ld * SSTRIDE, tid, A, B, bm, bn, K, N, kt + STAGES - 1);
        CP_COMMIT();

        uint32_t st = sb + slot * SSTRIDE;

        // hoist ALL 16 ldsm of the stage (both u-steps) ahead of all 64 MMAs
        uint32_t a[2][4][4], b[2][8][2];
        #pragma unroll
        for (int u = 0; u < 2; u++) {
            #pragma unroll
            for (int mt = 0; mt < 4; mt++)
                ldsm4(a[u][mt], st + A_OFF + (a_m + mt * 16) * APITCH + (u * 16 + a_k) * 2);
            #pragma unroll
            for (int nr = 0; nr < 4; nr++) {
                uint32_t r[4];
                ldsm4t(r, st + B_OFF + (u * 16 + b_k) * BPITCH + (b_n0 + nr * 16) * 2);
                b[u][nr * 2][0] = r[0]; b[u][nr * 2][1] = r[1];
                b[u][nr * 2 + 1][0] = r[2]; b[u][nr * 2 + 1][1] = r[3];
            }
        }
        #pragma unroll
        for (int u = 0; u < 2; u++)
            #pragma unroll
            for (int mt = 0; mt < 4; mt++)
                #pragma unroll
                for (int nt = 0; nt < 8; nt++)
                    mma_f16(acc[mt][nt], a[u][mt], b[u][nt]);

        slot = (slot == STAGES - 1) ? 0 : slot + 1;
        slot_ld = (slot_ld == STAGES - 1) ? 0 : slot_ld + 1;
    }

    // -------- epilogue --------
    int g = lane >> 2, tg = lane & 3;
    #pragma unroll
    for (int mt = 0; mt < 4; mt++) {
        #pragma unroll
        for (int half_ = 0; half_ < 2; half_++) {
            int row = bm + wm * 64 + mt * 16 + g + half_ * 8;
            float rs[NSTR], hp[NSTR];
            if (EPI == 2) {
                float4 r4 = *(const float4*)&g_rsum[row * NSTR];
                float4 h4 = *(const float4*)&g_hpost[row * NSTR];
                rs[0] = r4.x; rs[1] = r4.y; rs[2] = r4.z; rs[3] = r4.w;
                hp[0] = h4.x; hp[1] = h4.y; hp[2] = h4.z; hp[3] = h4.w;
            }
            #pragma unroll
            for (int nt = 0; nt < 8; nt++) {
                int col = bn + wn * 64 + nt * 8 + tg * 2;
                float2 bv = *(const float2*)&bias[col];
                float v0 = acc[mt][nt][half_ * 2 + 0] + bv.x;
                float v1 = acc[mt][nt][half_ * 2 + 1] + bv.y;
                if (EPI == 0) {
                    v0 = gelu_exact(v0);
                    v1 = gelu_exact(v1);
                    *(__half2*)&Ch[(size_t)row * N + col] =
                        __float22half2_rn(make_float2(v0, v1));
                } else if (EPI == 2) {
                    float2 xv = *(const float2*)&xin[(size_t)row * N + col];
                    #pragma unroll
                    for (int s = 0; s < NSTR; s++) {
                        float m0 = rs[s] * xv.x + hp[s] * v0;
                        float m1 = rs[s] * xv.y + hp[s] * v1;
                        *(__half2*)&Ch[(size_t)row * HID + s * C_DIM + col] =
                            __float22half2_rn(make_float2(m0, m1));
                    }
                } else {
                    float2 xv = *(const float2*)&xin[(size_t)row * N + col];
                    float2 o;
                    o.x = v0 + xv.x;
                    o.y = v1 + xv.y;
                    *(float2*)&outF[(size_t)row * N + col] = o;
                }
            }
        }
    }
}

// ---------------- launch ----------------
extern "C" void kernel_launch(void* const* d_in, const int* in_sizes, int n_in,
                              void* d_out, int out_size) {
    const float* x         = (const float*)d_in[0];
    const float* rms_w     = (const float*)d_in[1];
    const float* W_dyn     = (const float*)d_in[2];
    const float* bias_pre  = (const float*)d_in[3];
    const float* bias_post = (const float*)d_in[4];
    const float* bias_res  = (const float*)d_in[5];
    const float* alpha_pre = (const float*)d_in[6];
    const float* alpha_post= (const float*)d_in[7];
    const float* alpha_res = (const float*)d_in[8];
    const float* W1        = (const float*)d_in[9];
    const float* b1        = (const float*)d_in[10];
    const float* W2        = (const float*)d_in[11];
    const float* b2        = (const float*)d_in[12];
    const float* Wout      = (const float*)d_in[13];
    const float* bout      = (const float*)d_in[14];
    float* out = (float*)d_out;

    int T = in_sizes[0] / C_DIM;   // 8192

    __half *premix, *h, *merged, *w1h, *w2h, *woh;
    cudaGetSymbolAddress((void**)&premix, g_premix);
    cudaGetSymbolAddress((void**)&h, g_h);
    cudaGetSymbolAddress((void**)&merged, g_merged);
    cudaGetSymbolAddress((void**)&w1h, g_W1h);
    cudaGetSymbolAddress((void**)&w2h, g_W2h);
    cudaGetSymbolAddress((void**)&woh, g_Woh);

    cudaFuncSetAttribute(mma_gemm<0>, cudaFuncAttributeMaxDynamicSharedMemorySize, SMEM_TOTAL);
    cudaFuncSetAttribute(mma_gemm<2>, cudaFuncAttributeMaxDynamicSharedMemorySize, SMEM_TOTAL);
    cudaFuncSetAttribute(mma_gemm<3>, cudaFuncAttributeMaxDynamicSharedMemorySize, SMEM_TOTAL);

    // 1. prep
    weff_kernel<<<(C_DIM * NDC + 255) / 256, 256>>>(rms_w, W_dyn);
    cvt3_kernel<<<3072, 256>>>(W1, w1h, W2, w2h, Wout, woh, C_DIM * HID / 4);
    // 2. gates + sinkhorn + premix (warp per token)
    gates_kernel<<<T / 8, 256>>>(x, bias_pre, bias_post, bias_res,
                                 alpha_pre, alpha_post, alpha_res);
    // 3. h = gelu(premix @ W1 + b1)
    mma_gemm<0><<<dim3(HID / BN, T / BM), NTHREADS, SMEM_TOTAL>>>(
        premix, w1h, b1, nullptr, h, nullptr, T, HID, C_DIM);
    // 4. fout = h @ W2 + b2, fused merge -> merged
    mma_gemm<2><<<dim3(C_DIM / BN, T / BM), NTHREADS, SMEM_TOTAL>>>(
        h, w2h, b2, x, merged, nullptr, T, C_DIM, HID);
    // 5. out = merged @ Wout + bout + x
    mma_gemm<3><<<dim3(C_DIM / BN, T / BM), NTHREADS, SMEM_TOTAL>>>(
        merged, woh, bout, x, nullptr, out, T, C_DIM, HID);
}